// round 7
// baseline (speedup 1.0000x reference)
#include <cuda_runtime.h>
#include <cuda_fp16.h>

#define N_NODES 100000
#define N_EDGES 3200000
#define IN_CH 32
#define HID 16
#define SCAN_B 512
#define NB ((N_NODES + SCAN_B - 1) / SCAN_B)   // 196
#define NG ((N_NODES + 255) / 256)             // 391
#define EG2 ((N_EDGES / 2 + 255) / 256)        // 6250

// ---------------- device scratch (no allocs allowed) ----------------
// g_cnt is zero at process start (static init) and re-zeroed by scan_final
// after consumption -> every kernel_launch invocation sees zeros.
__device__ __half2 g_p1h[N_NODES][8];   // x @ Wl1.T  (fp16, 32B/row)
__device__ float   g_r1[N_NODES][HID];  // x @ Wr1.T
__device__ __half  g_p2h[N_NODES];      // h @ Wl2.T (fp16: L1-resident in gather2)
__device__ float   g_r2[N_NODES];       // h @ Wr2.T
__device__ int     g_cnt[N_NODES];      // in-degree histogram (self-restoring)
__device__ int     g_rowptr[N_NODES + 1];
__device__ int     g_woff[N_NODES];     // scatter write cursors
__device__ int     g_bsum[NB];          // per-block sums
__device__ int     g_srcs[N_EDGES];     // src ids bucketed by dst
__device__ int     g_idx64;             // 1 if edge_index is int64

// ---------------- K1: dtype detection (1 block) ----------------
__global__ void detect_kernel(const int* __restrict__ ei32) {
    __shared__ int s_or;
    if (threadIdx.x == 0) s_or = 0;
    __syncthreads();
    if (ei32[2 * threadIdx.x + 1] != 0) atomicOr(&s_or, 1);
    __syncthreads();
    if (threadIdx.x == 0) g_idx64 = (s_or == 0) ? 1 : 0;
}

// ---------------- paired edge loads (2 edges per thread) ----------------
__device__ __forceinline__ void load_dst2(const void* ei, int pair, int& d0, int& d1) {
    if (g_idx64) {
        longlong2 p = __ldg(reinterpret_cast<const longlong2*>(
                                (const long long*)ei + N_EDGES) + pair);
        d0 = (int)p.x; d1 = (int)p.y;
    } else {
        int2 p = __ldg(reinterpret_cast<const int2*>(
                           (const int*)ei + N_EDGES) + pair);
        d0 = p.x; d1 = p.y;
    }
}

__device__ __forceinline__ void load_src2(const void* ei, int pair, int& s0, int& s1) {
    if (g_idx64) {
        longlong2 p = __ldg(reinterpret_cast<const longlong2*>(
                                (const long long*)ei) + pair);
        s0 = (int)p.x; s1 = (int)p.y;
    } else {
        int2 p = __ldg(reinterpret_cast<const int2*>((const int*)ei) + pair);
        s0 = p.x; s1 = p.y;
    }
}

// ---------------- K2: histogram (2 edges/thread) ----------------
__global__ void __launch_bounds__(256) hist_kernel(const void* __restrict__ ei) {
    int pair = blockIdx.x * blockDim.x + threadIdx.x;
    if (pair >= N_EDGES / 2) return;
    int d0, d1;
    load_dst2(ei, pair, d0, d1);
    atomicAdd(&g_cnt[d0], 1);
    atomicAdd(&g_cnt[d1], 1);
}

// ---------------- K3: proj1: p1 = x@Wl1.T (fp16), r1 = x@Wr1.T ----------
__global__ void __launch_bounds__(256) proj1_kernel(
        const float* __restrict__ x,
        const float* __restrict__ Wl1,
        const float* __restrict__ Wr1) {
    __shared__ float sWl[HID * IN_CH];
    __shared__ float sWr[HID * IN_CH];
    for (int t = threadIdx.x; t < HID * IN_CH; t += 256) {
        sWl[t] = Wl1[t];
        sWr[t] = Wr1[t];
    }
    __syncthreads();
    int i = blockIdx.x * 256 + threadIdx.x;
    if (i >= N_NODES) return;

    float xr[IN_CH];
    const float4* xp = reinterpret_cast<const float4*>(x + (size_t)i * IN_CH);
#pragma unroll
    for (int j = 0; j < IN_CH / 4; j++) {
        float4 v = __ldg(&xp[j]);
        xr[4 * j + 0] = v.x; xr[4 * j + 1] = v.y;
        xr[4 * j + 2] = v.z; xr[4 * j + 3] = v.w;
    }
    float pl[HID];
#pragma unroll
    for (int k = 0; k < HID; k++) {
        float a = 0.0f, b = 0.0f;
#pragma unroll
        for (int j = 0; j < IN_CH; j++) {
            a = fmaf(xr[j], sWl[k * IN_CH + j], a);
            b = fmaf(xr[j], sWr[k * IN_CH + j], b);
        }
        pl[k] = a;
        g_r1[i][k] = b;
    }
#pragma unroll
    for (int j = 0; j < 8; j++)
        g_p1h[i][j] = __floats2half2_rn(pl[2 * j], pl[2 * j + 1]);
}

// ---------------- K4: per-block sums of g_cnt ----------------
__global__ void scan_reduce_kernel() {
    int t = blockIdx.x * SCAN_B + threadIdx.x;
    int v = (t < N_NODES) ? g_cnt[t] : 0;
    int lane = threadIdx.x & 31, wid = threadIdx.x >> 5;
#pragma unroll
    for (int o = 16; o; o >>= 1) v += __shfl_down_sync(0xffffffffu, v, o);
    __shared__ int s[16];
    if (lane == 0) s[wid] = v;
    __syncthreads();
    if (wid == 0) {
        int w = (lane < 16) ? s[lane] : 0;
#pragma unroll
        for (int o = 8; o; o >>= 1) w += __shfl_down_sync(0xffffffffu, w, o);
        if (lane == 0) g_bsum[blockIdx.x] = w;
    }
}

// ---------------- K5: final scan: prefix + tile scan + zero cnt ----------
__global__ void scan_final_kernel() {
    int lane = threadIdx.x & 31, wid = threadIdx.x >> 5;

    // block prefix = sum of g_bsum[0 .. blockIdx)
    __shared__ int s_pref;
    {
        int t = threadIdx.x;
        int v = (t < blockIdx.x) ? g_bsum[t] : 0;   // blockIdx <= NB
#pragma unroll
        for (int o = 16; o; o >>= 1) v += __shfl_down_sync(0xffffffffu, v, o);
        __shared__ int s[16];
        if (lane == 0) s[wid] = v;
        __syncthreads();
        if (wid == 0) {
            int w = (lane < 16) ? s[lane] : 0;
#pragma unroll
            for (int o = 8; o; o >>= 1) w += __shfl_down_sync(0xffffffffu, w, o);
            if (lane == 0) s_pref = w;
        }
        __syncthreads();
    }

    // tile scan (exclusive) + restore g_cnt to zero for the next run
    int t = blockIdx.x * SCAN_B + threadIdx.x;
    int v = (t < N_NODES) ? g_cnt[t] : 0;
    if (t < N_NODES) g_cnt[t] = 0;
    int sv = v;
#pragma unroll
    for (int off = 1; off < 32; off <<= 1) {
        int n = __shfl_up_sync(0xffffffffu, sv, off);
        if (lane >= off) sv += n;
    }
    __shared__ int wsum[16];
    if (lane == 31) wsum[wid] = sv;
    __syncthreads();
    if (wid == 0 && lane < 16) {
        int w = wsum[lane], sw = w;
#pragma unroll
        for (int off = 1; off < 16; off <<= 1) {
            int n = __shfl_up_sync(0xffffu, sw, off);
            if (lane >= off) sw += n;
        }
        wsum[lane] = sw - w;  // exclusive across warps
    }
    __syncthreads();
    int excl = sv - v + wsum[wid] + s_pref;
    if (t < N_NODES) {
        g_rowptr[t] = excl;
        g_woff[t] = excl;
    }
    if (blockIdx.x == 0 && threadIdx.x == 0) g_rowptr[N_NODES] = N_EDGES;
}

// ---------------- K6: scatter src ids (2 edges/thread) ----------------
__global__ void __launch_bounds__(256) scatter_kernel(const void* __restrict__ ei) {
    int pair = blockIdx.x * blockDim.x + threadIdx.x;
    if (pair >= N_EDGES / 2) return;
    int s0, s1, d0, d1;
    load_src2(ei, pair, s0, s1);
    load_dst2(ei, pair, d0, d1);
    int p0 = atomicAdd(&g_woff[d0], 1);
    g_srcs[p0] = s0;
    int p1 = atomicAdd(&g_woff[d1], 1);
    g_srcs[p1] = s1;
}

// ---------------- K7: gather layer 1 (fp16 p1, 16 edges in flight) -------
__global__ void __launch_bounds__(256) gather1_kernel(
        const float* __restrict__ b1,
        const float* __restrict__ Wl2,
        const float* __restrict__ Wr2) {
    int warp = (blockIdx.x * blockDim.x + threadIdx.x) >> 5;
    int lane = threadIdx.x & 31;
    if (warp >= N_NODES) return;
    int node = warp;
    int start = __ldg(&g_rowptr[node]);
    int end = __ldg(&g_rowptr[node + 1]);
    int g = lane >> 1;
    int c = lane & 1;

    float acc[8] = {0, 0, 0, 0, 0, 0, 0, 0};
    for (int e = start + g; e < end; e += 16) {
        int s = __ldg(&g_srcs[e]);
        int4 v = __ldg(reinterpret_cast<const int4*>(&g_p1h[s][0]) + c);
        float2 f0 = __half22float2(*(__half2*)&v.x);
        float2 f1 = __half22float2(*(__half2*)&v.y);
        float2 f2 = __half22float2(*(__half2*)&v.z);
        float2 f3 = __half22float2(*(__half2*)&v.w);
        acc[0] += f0.x; acc[1] += f0.y;
        acc[2] += f1.x; acc[3] += f1.y;
        acc[4] += f2.x; acc[5] += f2.y;
        acc[6] += f3.x; acc[7] += f3.y;
    }
#pragma unroll
    for (int off = 16; off >= 2; off >>= 1) {
#pragma unroll
        for (int j = 0; j < 8; j++)
            acc[j] += __shfl_down_sync(0xffffffffu, acc[j], off);
    }

    float dinv = 1.0f / fmaxf((float)(end - start), 1.0f);
    float p2 = 0.0f, r2 = 0.0f;
    int cbase = (lane & 1) * 8;
#pragma unroll
    for (int j = 0; j < 8; j++) {
        int ch = cbase + j;
        float h = fmaf(acc[j], dinv, __ldg(&b1[ch]) + g_r1[node][ch]);
        h = fmaxf(h, 0.0f);
        p2 = fmaf(h, __ldg(&Wl2[ch]), p2);
        r2 = fmaf(h, __ldg(&Wr2[ch]), r2);
    }
    p2 += __shfl_down_sync(0xffffffffu, p2, 1);
    r2 += __shfl_down_sync(0xffffffffu, r2, 1);
    if (lane == 0) {
        g_p2h[node] = __float2half(p2);
        g_r2[node] = r2;
    }
}

// ---------------- K8: gather layer 2 (fp16 p2, fused epilogue) ------------
__global__ void __launch_bounds__(256) gather2_kernel(
        const float* __restrict__ b2,
        float* __restrict__ out) {
    int warp = (blockIdx.x * blockDim.x + threadIdx.x) >> 5;
    int lane = threadIdx.x & 31;
    if (warp >= N_NODES) return;
    int start = __ldg(&g_rowptr[warp]);
    int end = __ldg(&g_rowptr[warp + 1]);
    float acc = 0.0f;
    for (int e = start + lane; e < end; e += 32)
        acc += __half2float(g_p2h[__ldg(&g_srcs[e])]);
#pragma unroll
    for (int o = 16; o; o >>= 1)
        acc += __shfl_down_sync(0xffffffffu, acc, o);
    if (lane == 0) {
        float dinv = 1.0f / fmaxf((float)(end - start), 1.0f);
        out[warp] = fmaf(acc, dinv, __ldg(&b2[0]) + g_r2[warp]);
    }
}

// ---------------- launch ----------------
extern "C" void kernel_launch(void* const* d_in, const int* in_sizes, int n_in,
                              void* d_out, int out_size) {
    const float* x   = (const float*)d_in[0];
    const void*  ei  = d_in[1];
    const float* Wl1 = (const float*)d_in[2];
    const float* Wr1 = (const float*)d_in[3];
    const float* b1  = (const float*)d_in[4];
    const float* Wl2 = (const float*)d_in[5];
    const float* Wr2 = (const float*)d_in[6];
    const float* b2  = (const float*)d_in[7];
    float* out = (float*)d_out;

    const int T = 256;
    const int WG = (N_NODES * 32 + T - 1) / T;  // 12500 (warp per node)

    detect_kernel<<<1, 256>>>((const int*)ei);
    hist_kernel<<<EG2, T>>>(ei);
    proj1_kernel<<<NG, T>>>(x, Wl1, Wr1);
    scan_reduce_kernel<<<NB, SCAN_B>>>();
    scan_final_kernel<<<NB, SCAN_B>>>();
    scatter_kernel<<<EG2, T>>>(ei);
    gather1_kernel<<<WG, T>>>(b1, Wl2, Wr2);
    gather2_kernel<<<WG, T>>>(b2, out);
}